// round 1
// baseline (speedup 1.0000x reference)
#include <cuda_runtime.h>
#include <math.h>

#define NTOK  32768
#define NCODE 8192
#define DIM   256
#define EPSF  1e-8f

#define BM 128
#define BN 128
#define BK 16
#define TM 8
#define TN 8

// Scratch (no allocations allowed anywhere)
__device__ float g_cnorm[NCODE];
__device__ int   g_min_idx[NTOK];
__device__ int   g_counts[NCODE];

__device__ __forceinline__ unsigned int f2ord(float f) {
    unsigned int u = __float_as_uint(f);
    return (u & 0x80000000u) ? ~u : (u | 0x80000000u);
}

// ---------------------------------------------------------------------------
// Zero the usage counts (graph-replay safe re-init)
// ---------------------------------------------------------------------------
__global__ void zero_counts_kernel() {
    int i = blockIdx.x * blockDim.x + threadIdx.x;
    if (i < NCODE) g_counts[i] = 0;
}

// ---------------------------------------------------------------------------
// ||c||^2 per codebook row: one warp per code
// ---------------------------------------------------------------------------
__global__ void cnorm_kernel(const float* __restrict__ cb) {
    int warp = (blockIdx.x * blockDim.x + threadIdx.x) >> 5;
    int lane = threadIdx.x & 31;
    if (warp >= NCODE) return;
    const float4* row = (const float4*)(cb + (size_t)warp * DIM);
    float s = 0.f;
#pragma unroll
    for (int i = 0; i < 2; i++) {
        float4 v = row[lane + 32 * i];
        s += v.x * v.x + v.y * v.y + v.z * v.z + v.w * v.w;
    }
#pragma unroll
    for (int o = 16; o; o >>= 1) s += __shfl_xor_sync(0xffffffffu, s, o);
    if (lane == 0) g_cnorm[warp] = s;
}

// ---------------------------------------------------------------------------
// Argmin GEMM: for each token row, argmin_n ( ||c_n||^2 - 2 * x . c_n )
// Classic 128x128x16 shared-memory SGEMM, 256 threads, 8x8 micro-tiles.
// Each CTA owns a 128-token tile and loops over all 8192 codes (no atomics).
// ---------------------------------------------------------------------------
__global__ __launch_bounds__(256, 2)
void argmin_kernel(const float* __restrict__ X, const float* __restrict__ C) {
    __shared__ __align__(16) float As[BK][BM];
    __shared__ __align__(16) float Bs[BK][BN];
    __shared__ unsigned long long red[BM][17];

    const int m0  = blockIdx.x * BM;
    const int tid = threadIdx.x;
    const int tx  = tid & 15;   // 0..15  -> n micro-tile
    const int ty  = tid >> 4;   // 0..15  -> m micro-tile

    unsigned long long best[TM];
#pragma unroll
    for (int i = 0; i < TM; i++) best[i] = ~0ull;

    for (int n0 = 0; n0 < NCODE; n0 += BN) {
        float acc[TM][TN];
#pragma unroll
        for (int i = 0; i < TM; i++)
#pragma unroll
            for (int j = 0; j < TN; j++) acc[i][j] = 0.f;

        for (int k0 = 0; k0 < DIM; k0 += BK) {
            // Load A tile (tokens) and B tile (codes), both [128 rows x 16 k],
            // stored transposed into As[k][m] / Bs[k][n].
#pragma unroll
            for (int r = 0; r < 2; r++) {
                int v   = tid + r * 256;       // float4 slot 0..511
                int row = v >> 2;              // 0..127
                int kq  = (v & 3) * 4;         // 0,4,8,12
                float4 a = *(const float4*)(X + (size_t)(m0 + row) * DIM + k0 + kq);
                As[kq + 0][row] = a.x;
                As[kq + 1][row] = a.y;
                As[kq + 2][row] = a.z;
                As[kq + 3][row] = a.w;
                float4 b = *(const float4*)(C + (size_t)(n0 + row) * DIM + k0 + kq);
                Bs[kq + 0][row] = b.x;
                Bs[kq + 1][row] = b.y;
                Bs[kq + 2][row] = b.z;
                Bs[kq + 3][row] = b.w;
            }
            __syncthreads();

#pragma unroll
            for (int k = 0; k < BK; k++) {
                float4 a0 = *(const float4*)&As[k][ty * TM];
                float4 a1 = *(const float4*)&As[k][ty * TM + 4];
                float4 b0 = *(const float4*)&Bs[k][tx * TN];
                float4 b1 = *(const float4*)&Bs[k][tx * TN + 4];
                float af[TM] = {a0.x, a0.y, a0.z, a0.w, a1.x, a1.y, a1.z, a1.w};
                float bf[TN] = {b0.x, b0.y, b0.z, b0.w, b1.x, b1.y, b1.z, b1.w};
#pragma unroll
                for (int i = 0; i < TM; i++)
#pragma unroll
                    for (int j = 0; j < TN; j++)
                        acc[i][j] = fmaf(af[i], bf[j], acc[i][j]);
            }
            __syncthreads();
        }

        // Epilogue for this N tile: d = ||c||^2 - 2 * dot ; packed argmin
        float cn[TN];
#pragma unroll
        for (int j = 0; j < TN; j++) cn[j] = g_cnorm[n0 + tx * TN + j];
#pragma unroll
        for (int i = 0; i < TM; i++) {
#pragma unroll
            for (int j = 0; j < TN; j++) {
                float d = fmaf(-2.f, acc[i][j], cn[j]);
                unsigned long long p =
                    ((unsigned long long)f2ord(d) << 32) |
                    (unsigned int)(n0 + tx * TN + j);
                best[i] = min(best[i], p);
            }
        }
    }

    // Cross-thread reduction: 16 tx threads share each m row
#pragma unroll
    for (int i = 0; i < TM; i++) red[ty * TM + i][tx] = best[i];
    __syncthreads();
    if (tid < BM) {
        unsigned long long b = red[tid][0];
#pragma unroll
        for (int t = 1; t < 16; t++) b = min(b, red[tid][t]);
        g_min_idx[m0 + tid] = (int)(b & 0xffffffffu);
    }
}

// ---------------------------------------------------------------------------
// Epilogue: one warp per token. Gather hard_q, compute r_norm / n_norm,
// write quantized = x + (r_norm/(n_norm+eps)) * rand. Count codebook usage.
// ---------------------------------------------------------------------------
__global__ void epilogue_kernel(const float* __restrict__ X,
                                const float* __restrict__ R,
                                const float* __restrict__ C,
                                float* __restrict__ out) {
    int warp = (blockIdx.x * blockDim.x + threadIdx.x) >> 5;
    int lane = threadIdx.x & 31;
    if (warp >= NTOK) return;

    int idx = g_min_idx[warp];
    if (lane == 0) atomicAdd(&g_counts[idx], 1);

    const float4* xr = (const float4*)(X + (size_t)warp * DIM);
    const float4* rr = (const float4*)(R + (size_t)warp * DIM);
    const float4* cr = (const float4*)(C + (size_t)idx * DIM);

    float4 xs[2], rs[2];
    float r2 = 0.f, n2 = 0.f;
#pragma unroll
    for (int i = 0; i < 2; i++) {
        float4 x = xr[lane + 32 * i];
        float4 c = cr[lane + 32 * i];
        float4 r = rr[lane + 32 * i];
        xs[i] = x; rs[i] = r;
        float dx = x.x - c.x, dy = x.y - c.y, dz = x.z - c.z, dw = x.w - c.w;
        r2 += dx * dx + dy * dy + dz * dz + dw * dw;
        n2 += r.x * r.x + r.y * r.y + r.z * r.z + r.w * r.w;
    }
#pragma unroll
    for (int o = 16; o; o >>= 1) {
        r2 += __shfl_xor_sync(0xffffffffu, r2, o);
        n2 += __shfl_xor_sync(0xffffffffu, n2, o);
    }
    float scale = sqrtf(r2) / (sqrtf(n2) + EPSF);

    float4* orow = (float4*)(out + (size_t)warp * DIM);
#pragma unroll
    for (int i = 0; i < 2; i++) {
        float4 x = xs[i], r = rs[i], o4;
        o4.x = fmaf(scale, r.x, x.x);
        o4.y = fmaf(scale, r.y, x.y);
        o4.z = fmaf(scale, r.z, x.z);
        o4.w = fmaf(scale, r.w, x.w);
        orow[lane + 32 * i] = o4;
    }
}

// ---------------------------------------------------------------------------
// Perplexity + unique count: single block over the 8192 counters.
// ---------------------------------------------------------------------------
__global__ void finalize_kernel(float* __restrict__ out, int out_size) {
    __shared__ float s_ent[32];
    __shared__ int   s_uni[32];
    int tid = threadIdx.x;

    float ent = 0.f;
    int   uni = 0;
    for (int i = tid; i < NCODE; i += blockDim.x) {
        int c = g_counts[i];
        if (c > 0) {
            uni++;
            float p = (float)c * (1.0f / (float)NTOK);
            ent += p * logf(p + EPSF);
        }
    }
#pragma unroll
    for (int o = 16; o; o >>= 1) {
        ent += __shfl_xor_sync(0xffffffffu, ent, o);
        uni += __shfl_xor_sync(0xffffffffu, uni, o);
    }
    int warp = tid >> 5, lane = tid & 31;
    if (lane == 0) { s_ent[warp] = ent; s_uni[warp] = uni; }
    __syncthreads();
    if (warp == 0) {
        int nw = (blockDim.x + 31) >> 5;
        ent = (lane < nw) ? s_ent[lane] : 0.f;
        uni = (lane < nw) ? s_uni[lane] : 0;
#pragma unroll
        for (int o = 16; o; o >>= 1) {
            ent += __shfl_xor_sync(0xffffffffu, ent, o);
            uni += __shfl_xor_sync(0xffffffffu, uni, o);
        }
        if (lane == 0) {
            long long base = (long long)NTOK * DIM;
            if (out_size > base)     out[base]     = expf(-ent);
            if (out_size > base + 1) out[base + 1] = (float)uni;
        }
    }
}

// ---------------------------------------------------------------------------
extern "C" void kernel_launch(void* const* d_in, const int* in_sizes, int n_in,
                              void* d_out, int out_size) {
    const float* X = (const float*)d_in[0];   // input_data (32768, 256)
    const float* R = (const float*)d_in[1];   // rand       (32768, 256)
    const float* C = (const float*)d_in[2];   // codebooks  (8192, 256)
    float* out = (float*)d_out;

    zero_counts_kernel<<<(NCODE + 255) / 256, 256>>>();
    cnorm_kernel<<<(NCODE * 32) / 256, 256>>>(C);
    argmin_kernel<<<NTOK / BM, 256>>>(X, C);
    epilogue_kernel<<<(NTOK * 32) / 256, 256>>>(X, R, C, out);
    finalize_kernel<<<1, 1024>>>(out, out_size);
}

// round 3
// speedup vs baseline: 3.3824x; 3.3824x over previous
#include <cuda_runtime.h>
#include <math.h>
#include <stdint.h>

#define NTOK  32768
#define NCODE 8192
#define DIM   256
#define EPSF  1e-8f

#define BM 128
#define BN 128
#define BK 32
#define NTILE (NCODE / BN)     // 64
#define KSTEPS (DIM / BK)      // 8
#define THREADS 256
#define PAD 36                 // floats per smem row (conflict-free fragments)

// ---- scratch (no allocations allowed) ----
__device__ float g_cnorm[NCODE];
__device__ int   g_min_idx[NTOK];
__device__ int   g_counts[NCODE];

__device__ __forceinline__ uint32_t f2tf32(float f) {
    uint32_t r;
    asm("cvt.rna.tf32.f32 %0, %1;" : "=r"(r) : "f"(f));
    return r;
}
__device__ __forceinline__ unsigned int f2ord(float f) {
    unsigned int u = __float_as_uint(f);
    return (u & 0x80000000u) ? ~u : (u | 0x80000000u);
}
__device__ __forceinline__ void mma_tf32(float& c0, float& c1, float& c2, float& c3,
                                         uint32_t a0, uint32_t a1, uint32_t a2, uint32_t a3,
                                         uint32_t b0, uint32_t b1) {
    asm volatile(
        "mma.sync.aligned.m16n8k8.row.col.f32.tf32.tf32.f32 "
        "{%0,%1,%2,%3}, {%4,%5,%6,%7}, {%8,%9}, {%0,%1,%2,%3};"
        : "+f"(c0), "+f"(c1), "+f"(c2), "+f"(c3)
        : "r"(a0), "r"(a1), "r"(a2), "r"(a3), "r"(b0), "r"(b1));
}

// ---------------------------------------------------------------------------
__global__ void zero_counts_kernel() {
    int i = blockIdx.x * blockDim.x + threadIdx.x;
    if (i < NCODE) g_counts[i] = 0;
}

__global__ void cnorm_kernel(const float* __restrict__ cb) {
    int warp = (blockIdx.x * blockDim.x + threadIdx.x) >> 5;
    int lane = threadIdx.x & 31;
    if (warp >= NCODE) return;
    const float4* row = (const float4*)(cb + (size_t)warp * DIM);
    float s = 0.f;
#pragma unroll
    for (int i = 0; i < 2; i++) {
        float4 v = row[lane + 32 * i];
        s += v.x * v.x + v.y * v.y + v.z * v.z + v.w * v.w;
    }
#pragma unroll
    for (int o = 16; o; o >>= 1) s += __shfl_xor_sync(0xffffffffu, s, o);
    if (lane == 0) g_cnorm[warp] = s;
}

// ---------------------------------------------------------------------------
// tf32 mma.sync argmin GEMM. One CTA = 128 tokens, loops all 64 code tiles.
// 8 warps as 2(m) x 4(n); warp tile 64x32; m16n8k8 tf32 HMMA.
// ---------------------------------------------------------------------------
__global__ __launch_bounds__(THREADS, 2)
void argmin_mma_kernel(const float* __restrict__ X, const float* __restrict__ C) {
    // As/Bs live during the tile loop; `red` (union) only after the final sync.
    __shared__ __align__(16) char smraw[2 * BM * PAD * 4];   // 36864 B
    uint32_t (*As)[PAD] = (uint32_t (*)[PAD])smraw;
    uint32_t (*Bs)[PAD] = (uint32_t (*)[PAD])(smraw + BM * PAD * 4);
    unsigned long long (*red)[17] = (unsigned long long (*)[17])smraw;

    const int tid  = threadIdx.x;
    const int lane = tid & 31;
    const int wid  = tid >> 5;
    const int wm   = wid >> 2;          // 0..1
    const int wn   = wid & 3;           // 0..3
    const int lr   = lane >> 2;         // 0..7
    const int lk   = lane & 3;          // 0..3
    const int m0   = blockIdx.x * BM;

    unsigned long long best[8];
#pragma unroll
    for (int i = 0; i < 8; i++) best[i] = ~0ull;

    for (int t = 0; t < NTILE; t++) {
        const int n0 = t * BN;
        float acc[4][4][4];
#pragma unroll
        for (int mt = 0; mt < 4; mt++)
#pragma unroll
            for (int nt = 0; nt < 4; nt++)
#pragma unroll
                for (int e = 0; e < 4; e++) acc[mt][nt][e] = 0.f;

        for (int k0 = 0; k0 < KSTEPS; k0++) {
            __syncthreads();
            // Stage A (tokens) and B (codes) 128x32 tiles, cvt to tf32.
#pragma unroll
            for (int r = 0; r < 4; r++) {
                int i   = tid + r * THREADS;    // 0..1023
                int row = i >> 3;               // 0..127
                int q   = i & 7;                // float4 within 32-K chunk
                float4 a = *(const float4*)(X + (size_t)(m0 + row) * DIM + k0 * BK + q * 4);
                uint4 ta = { f2tf32(a.x), f2tf32(a.y), f2tf32(a.z), f2tf32(a.w) };
                *(uint4*)&As[row][q * 4] = ta;
                float4 b = *(const float4*)(C + (size_t)(n0 + row) * DIM + k0 * BK + q * 4);
                uint4 tb = { f2tf32(b.x), f2tf32(b.y), f2tf32(b.z), f2tf32(b.w) };
                *(uint4*)&Bs[row][q * 4] = tb;
            }
            __syncthreads();

#pragma unroll
            for (int kk = 0; kk < 4; kk++) {
                const int kb = kk * 8 + lk;
                uint32_t af[4][4];
#pragma unroll
                for (int mt = 0; mt < 4; mt++) {
                    int rowa = wm * 64 + mt * 16 + lr;
                    af[mt][0] = As[rowa][kb];
                    af[mt][1] = As[rowa + 8][kb];
                    af[mt][2] = As[rowa][kb + 4];
                    af[mt][3] = As[rowa + 8][kb + 4];
                }
                uint32_t bf[4][2];
#pragma unroll
                for (int nt = 0; nt < 4; nt++) {
                    int rowb = wn * 32 + nt * 8 + lr;
                    bf[nt][0] = Bs[rowb][kb];
                    bf[nt][1] = Bs[rowb][kb + 4];
                }
#pragma unroll
                for (int mt = 0; mt < 4; mt++)
#pragma unroll
                    for (int nt = 0; nt < 4; nt++)
                        mma_tf32(acc[mt][nt][0], acc[mt][nt][1],
                                 acc[mt][nt][2], acc[mt][nt][3],
                                 af[mt][0], af[mt][1], af[mt][2], af[mt][3],
                                 bf[nt][0], bf[nt][1]);
            }
        }

        // Per-tile argmin epilogue: d = ||c||^2 - 2*dot
#pragma unroll
        for (int nt = 0; nt < 4; nt++) {
            int col = n0 + wn * 32 + nt * 8 + 2 * lk;
            float cn0 = __ldg(&g_cnorm[col]);
            float cn1 = __ldg(&g_cnorm[col + 1]);
#pragma unroll
            for (int mt = 0; mt < 4; mt++) {
#pragma unroll
                for (int h = 0; h < 2; h++) {
                    float d0 = fmaf(-2.f, acc[mt][nt][2 * h], cn0);
                    float d1 = fmaf(-2.f, acc[mt][nt][2 * h + 1], cn1);
                    unsigned long long p0 =
                        ((unsigned long long)f2ord(d0) << 32) | (unsigned int)col;
                    unsigned long long p1 =
                        ((unsigned long long)f2ord(d1) << 32) | (unsigned int)(col + 1);
                    unsigned long long p = min(p0, p1);
                    int bi = mt * 2 + h;
                    best[bi] = min(best[bi], p);
                }
            }
        }
    }

    // Cross-thread reduction (red overlays As/Bs — safe after this sync)
    __syncthreads();
#pragma unroll
    for (int mt = 0; mt < 4; mt++)
#pragma unroll
        for (int h = 0; h < 2; h++)
            red[wm * 64 + mt * 16 + h * 8 + lr][wn * 4 + lk] = best[mt * 2 + h];
    __syncthreads();
    if (tid < BM) {
        unsigned long long b = red[tid][0];
#pragma unroll
        for (int s = 1; s < 16; s++) b = min(b, red[tid][s]);
        g_min_idx[m0 + tid] = (int)(b & 0xffffffffu);
    }
}

// ---------------------------------------------------------------------------
// Epilogue: one warp per token
// ---------------------------------------------------------------------------
__global__ void epilogue_kernel(const float* __restrict__ X,
                                const float* __restrict__ R,
                                const float* __restrict__ C,
                                float* __restrict__ out) {
    int warp = (blockIdx.x * blockDim.x + threadIdx.x) >> 5;
    int lane = threadIdx.x & 31;
    if (warp >= NTOK) return;

    int idx = g_min_idx[warp];
    if (lane == 0) atomicAdd(&g_counts[idx], 1);

    const float4* xr = (const float4*)(X + (size_t)warp * DIM);
    const float4* rr = (const float4*)(R + (size_t)warp * DIM);
    const float4* cr = (const float4*)(C + (size_t)idx * DIM);

    float4 xs[2], rs[2];
    float r2 = 0.f, n2 = 0.f;
#pragma unroll
    for (int i = 0; i < 2; i++) {
        float4 x = xr[lane + 32 * i];
        float4 c = cr[lane + 32 * i];
        float4 r = rr[lane + 32 * i];
        xs[i] = x; rs[i] = r;
        float dx = x.x - c.x, dy = x.y - c.y, dz = x.z - c.z, dw = x.w - c.w;
        r2 += dx * dx + dy * dy + dz * dz + dw * dw;
        n2 += r.x * r.x + r.y * r.y + r.z * r.z + r.w * r.w;
    }
#pragma unroll
    for (int o = 16; o; o >>= 1) {
        r2 += __shfl_xor_sync(0xffffffffu, r2, o);
        n2 += __shfl_xor_sync(0xffffffffu, n2, o);
    }
    float scale = sqrtf(r2) / (sqrtf(n2) + EPSF);

    float4* orow = (float4*)(out + (size_t)warp * DIM);
#pragma unroll
    for (int i = 0; i < 2; i++) {
        float4 x = xs[i], r = rs[i], o4;
        o4.x = fmaf(scale, r.x, x.x);
        o4.y = fmaf(scale, r.y, x.y);
        o4.z = fmaf(scale, r.z, x.z);
        o4.w = fmaf(scale, r.w, x.w);
        orow[lane + 32 * i] = o4;
    }
}

// ---------------------------------------------------------------------------
__global__ void finalize_kernel(float* __restrict__ out, int out_size) {
    __shared__ float s_ent[32];
    __shared__ int   s_uni[32];
    int tid = threadIdx.x;

    float ent = 0.f;
    int   uni = 0;
    for (int i = tid; i < NCODE; i += blockDim.x) {
        int c = g_counts[i];
        if (c > 0) {
            uni++;
            float p = (float)c * (1.0f / (float)NTOK);
            ent += p * logf(p + EPSF);
        }
    }
#pragma unroll
    for (int o = 16; o; o >>= 1) {
        ent += __shfl_xor_sync(0xffffffffu, ent, o);
        uni += __shfl_xor_sync(0xffffffffu, uni, o);
    }
    int warp = tid >> 5, lane = tid & 31;
    if (lane == 0) { s_ent[warp] = ent; s_uni[warp] = uni; }
    __syncthreads();
    if (warp == 0) {
        int nw = (blockDim.x + 31) >> 5;
        ent = (lane < nw) ? s_ent[lane] : 0.f;
        uni = (lane < nw) ? s_uni[lane] : 0;
#pragma unroll
        for (int o = 16; o; o >>= 1) {
            ent += __shfl_xor_sync(0xffffffffu, ent, o);
            uni += __shfl_xor_sync(0xffffffffu, uni, o);
        }
        if (lane == 0) {
            long long base = (long long)NTOK * DIM;
            if (out_size > base)     out[base]     = expf(-ent);
            if (out_size > base + 1) out[base + 1] = (float)uni;
        }
    }
}

// ---------------------------------------------------------------------------
extern "C" void kernel_launch(void* const* d_in, const int* in_sizes, int n_in,
                              void* d_out, int out_size) {
    const float* X = (const float*)d_in[0];   // input_data (32768, 256)
    const float* R = (const float*)d_in[1];   // rand       (32768, 256)
    const float* C = (const float*)d_in[2];   // codebooks  (8192, 256)
    float* out = (float*)d_out;

    zero_counts_kernel<<<(NCODE + 255) / 256, 256>>>();
    cnorm_kernel<<<(NCODE * 32) / 256, 256>>>(C);
    argmin_mma_kernel<<<NTOK / BM, THREADS>>>(X, C);
    epilogue_kernel<<<(NTOK * 32) / 256, 256>>>(X, R, C, out);
    finalize_kernel<<<1, 1024>>>(out, out_size);
}

// round 4
// speedup vs baseline: 7.1470x; 2.1130x over previous
#include <cuda_runtime.h>
#include <cuda_fp16.h>
#include <math.h>
#include <stdint.h>

#define NTOK  32768
#define NCODE 8192
#define DIM   256
#define EPSF  1e-8f

#define BM 128
#define BN 128
#define BK 64                    // K halfs per stage
#define NTILE (NCODE / BN)       // 64
#define KSTG  (DIM / BK)         // 4 stages per tile
#define NSTG  (NTILE * KSTG)     // 256 total stages
#define THREADS 256

// smem geometry (bytes): A resident 128 rows x 528B; B 2 bufs x 128 rows x 144B
#define A_STRIDE 528             // 264 halfs; 132 words -> bank (4*lr+lk) conflict-free
#define B_STRIDE 144             // 72 halfs; 36 words  -> bank (4*lr+lk) conflict-free
#define SM_A     0
#define SM_B     (BM * A_STRIDE)             // 67584
#define B_BUF    (BM * B_STRIDE)             // 18432
#define SM_TOTAL (SM_B + 2 * B_BUF)          // 104448

// ---- scratch (no allocations allowed) ----
__device__ __half g_xh[NTOK * DIM];          // 16 MB fp16 inputs
__device__ __half g_ch[NCODE * DIM];         //  4 MB fp16 codebooks
__device__ float  g_cnorm[NCODE];
__device__ int    g_min_idx[NTOK];
__device__ int    g_counts[NCODE];

__device__ __forceinline__ uint32_t smem_u32(const void* p) {
    uint32_t a;
    asm("{ .reg .u64 t; cvta.to.shared.u64 t, %1; cvt.u32.u64 %0, t; }"
        : "=r"(a) : "l"(p));
    return a;
}
__device__ __forceinline__ unsigned int f2ord(float f) {
    unsigned int u = __float_as_uint(f);
    return (u & 0x80000000u) ? ~u : (u | 0x80000000u);
}
#define CP_ASYNC16(dst, src) \
    asm volatile("cp.async.cg.shared.global [%0], [%1], 16;" :: "r"(dst), "l"(src))
#define CP_COMMIT() asm volatile("cp.async.commit_group;" ::: "memory")
#define CP_WAIT(n)  asm volatile("cp.async.wait_group %0;" :: "n"(n) : "memory")

__device__ __forceinline__ void mma_f16(float& c0, float& c1, float& c2, float& c3,
                                        uint32_t a0, uint32_t a1, uint32_t a2, uint32_t a3,
                                        uint32_t b0, uint32_t b1) {
    asm volatile(
        "mma.sync.aligned.m16n8k16.row.col.f32.f16.f16.f32 "
        "{%0,%1,%2,%3}, {%4,%5,%6,%7}, {%8,%9}, {%0,%1,%2,%3};"
        : "+f"(c0), "+f"(c1), "+f"(c2), "+f"(c3)
        : "r"(a0), "r"(a1), "r"(a2), "r"(a3), "r"(b0), "r"(b1));
}

// ---------------------------------------------------------------------------
__global__ void zero_counts_kernel() {
    int i = blockIdx.x * blockDim.x + threadIdx.x;
    if (i < NCODE) g_counts[i] = 0;
}

// Convert inputs + codebooks to fp16 (rn); one thread = 4 floats.
__global__ void convert_kernel(const float* __restrict__ X,
                               const float* __restrict__ C) {
    const int nx = NTOK * DIM / 4;
    const int nc = NCODE * DIM / 4;
    int i = blockIdx.x * blockDim.x + threadIdx.x;
    if (i < nx) {
        float4 v = ((const float4*)X)[i];
        __half2* o = (__half2*)(g_xh + (size_t)i * 4);
        o[0] = __floats2half2_rn(v.x, v.y);
        o[1] = __floats2half2_rn(v.z, v.w);
    } else if (i < nx + nc) {
        int j = i - nx;
        float4 v = ((const float4*)C)[j];
        __half2* o = (__half2*)(g_ch + (size_t)j * 4);
        o[0] = __floats2half2_rn(v.x, v.y);
        o[1] = __floats2half2_rn(v.z, v.w);
    }
}

__global__ void cnorm_kernel(const float* __restrict__ cb) {
    int warp = (blockIdx.x * blockDim.x + threadIdx.x) >> 5;
    int lane = threadIdx.x & 31;
    if (warp >= NCODE) return;
    const float4* row = (const float4*)(cb + (size_t)warp * DIM);
    float s = 0.f;
#pragma unroll
    for (int i = 0; i < 2; i++) {
        float4 v = row[lane + 32 * i];
        s += v.x * v.x + v.y * v.y + v.z * v.z + v.w * v.w;
    }
#pragma unroll
    for (int o = 16; o; o >>= 1) s += __shfl_xor_sync(0xffffffffu, s, o);
    if (lane == 0) g_cnorm[warp] = s;
}

// ---------------------------------------------------------------------------
// fp16 mma.sync argmin GEMM. A resident in smem, B cp.async double-buffered.
// 8 warps 2(m)x4(n); warp tile 64x32; m16n8k16.
// ---------------------------------------------------------------------------
__global__ __launch_bounds__(THREADS, 2)
void argmin_mma_kernel(void) {
    extern __shared__ __align__(16) char smem[];
    unsigned long long (*red)[17] = (unsigned long long (*)[17])smem;

    const int tid  = threadIdx.x;
    const int lane = tid & 31;
    const int wid  = tid >> 5;
    const int wm   = wid >> 2;          // 0..1
    const int wn   = wid & 3;           // 0..3
    const int lr   = lane >> 2;         // 0..7
    const int lk   = lane & 3;          // 0..3
    const int m0   = blockIdx.x * BM;

    const uint32_t sA = smem_u32(smem);
    const uint32_t sB = sA + SM_B;

    // Prefetch resident A: 128 rows x 512B = 4096 16B chunks
    {
        const __half* xa = g_xh + (size_t)m0 * DIM;
#pragma unroll
        for (int r = 0; r < 16; r++) {
            int c   = tid + r * THREADS;       // 0..4095
            int row = c >> 5, q = c & 31;
            CP_ASYNC16(sA + row * A_STRIDE + q * 16, xa + (size_t)row * DIM + q * 8);
        }
    }
    // Stage B(0)
#pragma unroll
    for (int r = 0; r < 4; r++) {
        int c   = tid + r * THREADS;           // 0..1023
        int row = c >> 3, q = c & 7;
        CP_ASYNC16(sB + row * B_STRIDE + q * 16,
                   g_ch + (size_t)row * DIM + q * 8);
    }
    CP_COMMIT();

    unsigned long long best[8];
#pragma unroll
    for (int i = 0; i < 8; i++) best[i] = ~0ull;

    float acc[4][4][4];

    for (int s = 0; s < NSTG; s++) {
        // prefetch next stage into the other buffer
        if (s + 1 < NSTG) {
            const int t1 = (s + 1) >> 2, k1 = (s + 1) & 3;
            const uint32_t d = sB + ((s + 1) & 1) * B_BUF;
            const __half* src = g_ch + (size_t)t1 * BN * DIM + k1 * BK;
#pragma unroll
            for (int r = 0; r < 4; r++) {
                int c   = tid + r * THREADS;
                int row = c >> 3, q = c & 7;
                CP_ASYNC16(d + row * B_STRIDE + q * 16,
                           src + (size_t)row * DIM + q * 8);
            }
            CP_COMMIT();
            CP_WAIT(1);
        } else {
            CP_WAIT(0);
        }
        __syncthreads();

        const int ks = s & 3;
        const uint32_t bb = sB + (s & 1) * B_BUF;

        if (ks == 0) {
#pragma unroll
            for (int mt = 0; mt < 4; mt++)
#pragma unroll
                for (int nt = 0; nt < 4; nt++)
#pragma unroll
                    for (int e = 0; e < 4; e++) acc[mt][nt][e] = 0.f;
        }

#pragma unroll
        for (int kk = 0; kk < 4; kk++) {
            uint32_t af[4][4];
#pragma unroll
            for (int mt = 0; mt < 4; mt++) {
                int rowa = wm * 64 + mt * 16 + lr;
                uint32_t a = sA + rowa * A_STRIDE + ks * 128 + kk * 32 + lk * 4;
                asm volatile("ld.shared.b32 %0, [%1];" : "=r"(af[mt][0]) : "r"(a));
                asm volatile("ld.shared.b32 %0, [%1];" : "=r"(af[mt][1]) : "r"(a + 8 * A_STRIDE));
                asm volatile("ld.shared.b32 %0, [%1];" : "=r"(af[mt][2]) : "r"(a + 16));
                asm volatile("ld.shared.b32 %0, [%1];" : "=r"(af[mt][3]) : "r"(a + 8 * A_STRIDE + 16));
            }
            uint32_t bf[4][2];
#pragma unroll
            for (int nt = 0; nt < 4; nt++) {
                int rowb = wn * 32 + nt * 8 + lr;
                uint32_t b = bb + rowb * B_STRIDE + kk * 32 + lk * 4;
                asm volatile("ld.shared.b32 %0, [%1];" : "=r"(bf[nt][0]) : "r"(b));
                asm volatile("ld.shared.b32 %0, [%1];" : "=r"(bf[nt][1]) : "r"(b + 16));
            }
#pragma unroll
            for (int mt = 0; mt < 4; mt++)
#pragma unroll
                for (int nt = 0; nt < 4; nt++)
                    mma_f16(acc[mt][nt][0], acc[mt][nt][1],
                            acc[mt][nt][2], acc[mt][nt][3],
                            af[mt][0], af[mt][1], af[mt][2], af[mt][3],
                            bf[nt][0], bf[nt][1]);
        }

        // tile finished -> argmin epilogue
        if (ks == 3) {
            const int n0 = (s >> 2) * BN;
#pragma unroll
            for (int nt = 0; nt < 4; nt++) {
                int col = n0 + wn * 32 + nt * 8 + 2 * lk;
                float cn0 = __ldg(&g_cnorm[col]);
                float cn1 = __ldg(&g_cnorm[col + 1]);
#pragma unroll
                for (int mt = 0; mt < 4; mt++) {
#pragma unroll
                    for (int h = 0; h < 2; h++) {
                        float d0 = fmaf(-2.f, acc[mt][nt][2 * h], cn0);
                        float d1 = fmaf(-2.f, acc[mt][nt][2 * h + 1], cn1);
                        unsigned long long p0 =
                            ((unsigned long long)f2ord(d0) << 32) | (unsigned int)col;
                        unsigned long long p1 =
                            ((unsigned long long)f2ord(d1) << 32) | (unsigned int)(col + 1);
                        unsigned long long p = min(p0, p1);
                        int bi = mt * 2 + h;
                        best[bi] = min(best[bi], p);
                    }
                }
            }
        }
        __syncthreads();   // protect buffer (s+1)&1 before next prefetch overwrites
    }

    // Cross-thread reduction (red overlays A region — safe after final sync)
#pragma unroll
    for (int mt = 0; mt < 4; mt++)
#pragma unroll
        for (int h = 0; h < 2; h++)
            red[wm * 64 + mt * 16 + h * 8 + lr][wn * 4 + lk] = best[mt * 2 + h];
    __syncthreads();
    if (tid < BM) {
        unsigned long long b = red[tid][0];
#pragma unroll
        for (int q = 1; q < 16; q++) b = min(b, red[tid][q]);
        g_min_idx[m0 + tid] = (int)(b & 0xffffffffu);
    }
}

// ---------------------------------------------------------------------------
// Epilogue: one warp per token (fp32 inputs, exact)
// ---------------------------------------------------------------------------
__global__ void epilogue_kernel(const float* __restrict__ X,
                                const float* __restrict__ R,
                                const float* __restrict__ C,
                                float* __restrict__ out) {
    int warp = (blockIdx.x * blockDim.x + threadIdx.x) >> 5;
    int lane = threadIdx.x & 31;
    if (warp >= NTOK) return;

    int idx = g_min_idx[warp];
    if (lane == 0) atomicAdd(&g_counts[idx], 1);

    const float4* xr = (const float4*)(X + (size_t)warp * DIM);
    const float4* rr = (const float4*)(R + (size_t)warp * DIM);
    const float4* cr = (const float4*)(C + (size_t)idx * DIM);

    float4 xs[2], rs[2];
    float r2 = 0.f, n2 = 0.f;
#pragma unroll
    for (int i = 0; i < 2; i++) {
        float4 x = xr[lane + 32 * i];
        float4 c = cr[lane + 32 * i];
        float4 r = rr[lane + 32 * i];
        xs[i] = x; rs[i] = r;
        float dx = x.x - c.x, dy = x.y - c.y, dz = x.z - c.z, dw = x.w - c.w;
        r2 += dx * dx + dy * dy + dz * dz + dw * dw;
        n2 += r.x * r.x + r.y * r.y + r.z * r.z + r.w * r.w;
    }
#pragma unroll
    for (int o = 16; o; o >>= 1) {
        r2 += __shfl_xor_sync(0xffffffffu, r2, o);
        n2 += __shfl_xor_sync(0xffffffffu, n2, o);
    }
    float scale = sqrtf(r2) / (sqrtf(n2) + EPSF);

    float4* orow = (float4*)(out + (size_t)warp * DIM);
#pragma unroll
    for (int i = 0; i < 2; i++) {
        float4 x = xs[i], r = rs[i], o4;
        o4.x = fmaf(scale, r.x, x.x);
        o4.y = fmaf(scale, r.y, x.y);
        o4.z = fmaf(scale, r.z, x.z);
        o4.w = fmaf(scale, r.w, x.w);
        orow[lane + 32 * i] = o4;
    }
}

// ---------------------------------------------------------------------------
__global__ void finalize_kernel(float* __restrict__ out, int out_size) {
    __shared__ float s_ent[32];
    __shared__ int   s_uni[32];
    int tid = threadIdx.x;

    float ent = 0.f;
    int   uni = 0;
    for (int i = tid; i < NCODE; i += blockDim.x) {
        int c = g_counts[i];
        if (c > 0) {
            uni++;
            float p = (float)c * (1.0f / (float)NTOK);
            ent += p * logf(p + EPSF);
        }
    }
#pragma unroll
    for (int o = 16; o; o >>= 1) {
        ent += __shfl_xor_sync(0xffffffffu, ent, o);
        uni += __shfl_xor_sync(0xffffffffu, uni, o);
    }
    int warp = tid >> 5, lane = tid & 31;
    if (lane == 0) { s_ent[warp] = ent; s_uni[warp] = uni; }
    __syncthreads();
    if (warp == 0) {
        int nw = (blockDim.x + 31) >> 5;
        ent = (lane < nw) ? s_ent[lane] : 0.f;
        uni = (lane < nw) ? s_uni[lane] : 0;
#pragma unroll
        for (int o = 16; o; o >>= 1) {
            ent += __shfl_xor_sync(0xffffffffu, ent, o);
            uni += __shfl_xor_sync(0xffffffffu, uni, o);
        }
        if (lane == 0) {
            long long base = (long long)NTOK * DIM;
            if (out_size > base)     out[base]     = expf(-ent);
            if (out_size > base + 1) out[base + 1] = (float)uni;
        }
    }
}

// ---------------------------------------------------------------------------
extern "C" void kernel_launch(void* const* d_in, const int* in_sizes, int n_in,
                              void* d_out, int out_size) {
    const float* X = (const float*)d_in[0];   // input_data (32768, 256)
    const float* R = (const float*)d_in[1];   // rand       (32768, 256)
    const float* C = (const float*)d_in[2];   // codebooks  (8192, 256)
    float* out = (float*)d_out;

    cudaFuncSetAttribute(argmin_mma_kernel,
                         cudaFuncAttributeMaxDynamicSharedMemorySize, SM_TOTAL);

    zero_counts_kernel<<<(NCODE + 255) / 256, 256>>>();
    convert_kernel<<<((NTOK + NCODE) * DIM / 4 + 255) / 256, 256>>>(X, C);
    cnorm_kernel<<<(NCODE * 32) / 256, 256>>>(C);
    argmin_mma_kernel<<<NTOK / BM, THREADS, SM_TOTAL>>>();
    epilogue_kernel<<<(NTOK * 32) / 256, 256>>>(X, R, C, out);
    finalize_kernel<<<1, 1024>>>(out, out_size);
}

// round 5
// speedup vs baseline: 8.5666x; 1.1986x over previous
#include <cuda_runtime.h>
#include <cuda_fp16.h>
#include <math.h>
#include <stdint.h>

#define NTOK  32768
#define NCODE 8192
#define DIM   256
#define EPSF  1e-8f

#define BM 128
#define BN 128
#define BK 64                    // K halfs per stage
#define NTILE (NCODE / BN)       // 64
#define NSTG  (NTILE * 4)        // 256 stages
#define THREADS 256

// smem geometry (bytes)
#define A_STRIDE 528             // 132 words; 132 mod 32 = 4 -> conflict-free ldmatrix
#define B_STRIDE 144             // 36 words;  36 mod 32 = 4 -> conflict-free ldmatrix
#define SM_B     (BM * A_STRIDE)             // 67584
#define B_BUF    (BM * B_STRIDE)             // 18432
#define SM_TOTAL (SM_B + 2 * B_BUF)          // 104448

// ---- scratch (no allocations allowed) ----
__device__ __half g_xh[NTOK * DIM];
__device__ __half g_ch[NCODE * DIM];
__device__ float  g_cnorm[NCODE];
__device__ int    g_min_idx[NTOK];
__device__ int    g_counts[NCODE];

__device__ __forceinline__ uint32_t smem_u32(const void* p) {
    uint32_t a;
    asm("{ .reg .u64 t; cvta.to.shared.u64 t, %1; cvt.u32.u64 %0, t; }"
        : "=r"(a) : "l"(p));
    return a;
}
__device__ __forceinline__ unsigned int f2ord(float f) {
    unsigned int u = __float_as_uint(f);
    return (u & 0x80000000u) ? ~u : (u | 0x80000000u);
}
#define CP_ASYNC16(dst, src) \
    asm volatile("cp.async.cg.shared.global [%0], [%1], 16;" :: "r"(dst), "l"(src))
#define CP_COMMIT() asm volatile("cp.async.commit_group;" ::: "memory")
#define CP_WAIT(n)  asm volatile("cp.async.wait_group %0;" :: "n"(n) : "memory")

#define LDSM_X4(r0, r1, r2, r3, addr) \
    asm volatile("ldmatrix.sync.aligned.m8n8.x4.shared.b16 {%0,%1,%2,%3}, [%4];" \
        : "=r"(r0), "=r"(r1), "=r"(r2), "=r"(r3) : "r"(addr))

__device__ __forceinline__ void mma_f16(float& c0, float& c1, float& c2, float& c3,
                                        uint32_t a0, uint32_t a1, uint32_t a2, uint32_t a3,
                                        uint32_t b0, uint32_t b1) {
    asm volatile(
        "mma.sync.aligned.m16n8k16.row.col.f32.f16.f16.f32 "
        "{%0,%1,%2,%3}, {%4,%5,%6,%7}, {%8,%9}, {%0,%1,%2,%3};"
        : "+f"(c0), "+f"(c1), "+f"(c2), "+f"(c3)
        : "r"(a0), "r"(a1), "r"(a2), "r"(a3), "r"(b0), "r"(b1));
}

// ---------------------------------------------------------------------------
__global__ void zero_counts_kernel() {
    int i = blockIdx.x * blockDim.x + threadIdx.x;
    if (i < NCODE) g_counts[i] = 0;
}

__global__ void convert_kernel(const float* __restrict__ X,
                               const float* __restrict__ C) {
    const int nx = NTOK * DIM / 4;
    const int nc = NCODE * DIM / 4;
    int i = blockIdx.x * blockDim.x + threadIdx.x;
    if (i < nx) {
        float4 v = ((const float4*)X)[i];
        __half2* o = (__half2*)(g_xh + (size_t)i * 4);
        o[0] = __floats2half2_rn(v.x, v.y);
        o[1] = __floats2half2_rn(v.z, v.w);
    } else if (i < nx + nc) {
        int j = i - nx;
        float4 v = ((const float4*)C)[j];
        __half2* o = (__half2*)(g_ch + (size_t)j * 4);
        o[0] = __floats2half2_rn(v.x, v.y);
        o[1] = __floats2half2_rn(v.z, v.w);
    }
}

__global__ void cnorm_kernel(const float* __restrict__ cb) {
    int warp = (blockIdx.x * blockDim.x + threadIdx.x) >> 5;
    int lane = threadIdx.x & 31;
    if (warp >= NCODE) return;
    const float4* row = (const float4*)(cb + (size_t)warp * DIM);
    float s = 0.f;
#pragma unroll
    for (int i = 0; i < 2; i++) {
        float4 v = row[lane + 32 * i];
        s += v.x * v.x + v.y * v.y + v.z * v.z + v.w * v.w;
    }
#pragma unroll
    for (int o = 16; o; o >>= 1) s += __shfl_xor_sync(0xffffffffu, s, o);
    if (lane == 0) g_cnorm[warp] = s;
}

// ---------------------------------------------------------------------------
// fp16 mma.sync argmin GEMM with ldmatrix fragment feeds.
// A resident in smem; B cp.async double-buffered; 8 warps 2(m)x4(n).
// ---------------------------------------------------------------------------
__global__ __launch_bounds__(THREADS, 2)
void argmin_mma_kernel(void) {
    extern __shared__ __align__(16) char smem[];
    unsigned long long (*red)[17] = (unsigned long long (*)[17])smem;

    const int tid  = threadIdx.x;
    const int lane = tid & 31;
    const int wid  = tid >> 5;
    const int wm   = wid >> 2;          // 0..1
    const int wn   = wid & 3;           // 0..3
    const int lr   = lane >> 2;         // 0..7
    const int lk   = lane & 3;          // 0..3
    const int m0   = blockIdx.x * BM;

    const uint32_t sA = smem_u32(smem);
    const uint32_t sB = sA + SM_B;

    // ldmatrix lane base addresses
    const uint32_t aBase = sA + (uint32_t)(wm * 64 + (lane & 15)) * A_STRIDE
                              + ((lane >> 4) & 1) * 16;
    const uint32_t bBase = (uint32_t)(wn * 32 + ((lane >> 4) & 1) * 8 + (lane & 7)) * B_STRIDE
                              + ((lane >> 3) & 1) * 16;

    // Prefetch resident A: 128 rows x 512B
    {
        const __half* xa = g_xh + (size_t)m0 * DIM;
#pragma unroll
        for (int r = 0; r < 16; r++) {
            int c   = tid + r * THREADS;
            int row = c >> 5, q = c & 31;
            CP_ASYNC16(sA + row * A_STRIDE + q * 16, xa + (size_t)row * DIM + q * 8);
        }
    }
    // Stage B(0)
#pragma unroll
    for (int r = 0; r < 4; r++) {
        int c   = tid + r * THREADS;
        int row = c >> 3, q = c & 7;
        CP_ASYNC16(sB + row * B_STRIDE + q * 16, g_ch + (size_t)row * DIM + q * 8);
    }
    CP_COMMIT();

    float bestd[8];
    int   besti[8];
#pragma unroll
    for (int i = 0; i < 8; i++) { bestd[i] = __int_as_float(0x7f800000); besti[i] = 0; }

    float acc[4][4][4];

    for (int s = 0; s < NSTG; s++) {
        if (s + 1 < NSTG) {
            const int t1 = (s + 1) >> 2, k1 = (s + 1) & 3;
            const uint32_t d = sB + ((s + 1) & 1) * B_BUF;
            const __half* src = g_ch + (size_t)t1 * BN * DIM + k1 * BK;
#pragma unroll
            for (int r = 0; r < 4; r++) {
                int c   = tid + r * THREADS;
                int row = c >> 3, q = c & 7;
                CP_ASYNC16(d + row * B_STRIDE + q * 16, src + (size_t)row * DIM + q * 8);
            }
            CP_COMMIT();
            CP_WAIT(1);
        } else {
            CP_WAIT(0);
        }
        __syncthreads();

        const int ks = s & 3;
        const uint32_t aK = aBase + ks * 128;                 // + kk*32 + mt*16*A_STRIDE
        const uint32_t bK = sB + (s & 1) * B_BUF + bBase;     // + kk*32 + pair*16*B_STRIDE

        if (ks == 0) {
#pragma unroll
            for (int mt = 0; mt < 4; mt++)
#pragma unroll
                for (int nt = 0; nt < 4; nt++)
#pragma unroll
                    for (int e = 0; e < 4; e++) acc[mt][nt][e] = 0.f;
        }

#pragma unroll
        for (int kk = 0; kk < 4; kk++) {
            uint32_t af[4][4];
#pragma unroll
            for (int mt = 0; mt < 4; mt++)
                LDSM_X4(af[mt][0], af[mt][1], af[mt][2], af[mt][3],
                        aK + kk * 32 + mt * (16 * A_STRIDE));
            uint32_t bf[4][2];
#pragma unroll
            for (int p = 0; p < 2; p++)
                LDSM_X4(bf[2 * p][0], bf[2 * p][1], bf[2 * p + 1][0], bf[2 * p + 1][1],
                        bK + kk * 32 + p * (16 * B_STRIDE));
#pragma unroll
            for (int mt = 0; mt < 4; mt++)
#pragma unroll
                for (int nt = 0; nt < 4; nt++)
                    mma_f16(acc[mt][nt][0], acc[mt][nt][1],
                            acc[mt][nt][2], acc[mt][nt][3],
                            af[mt][0], af[mt][1], af[mt][2], af[mt][3],
                            bf[nt][0], bf[nt][1]);
        }

        if (ks == 3) {
            const int n0 = (s >> 2) * BN;
#pragma unroll
            for (int nt = 0; nt < 4; nt++) {
                int col = n0 + wn * 32 + nt * 8 + 2 * lk;
                float cn0 = __ldg(&g_cnorm[col]);
                float cn1 = __ldg(&g_cnorm[col + 1]);
#pragma unroll
                for (int mt = 0; mt < 4; mt++) {
#pragma unroll
                    for (int h = 0; h < 2; h++) {
                        int bi = mt * 2 + h;
                        float d0 = fmaf(-2.f, acc[mt][nt][2 * h], cn0);
                        float d1 = fmaf(-2.f, acc[mt][nt][2 * h + 1], cn1);
                        if (d0 < bestd[bi]) { bestd[bi] = d0; besti[bi] = col; }
                        if (d1 < bestd[bi]) { bestd[bi] = d1; besti[bi] = col + 1; }
                    }
                }
            }
        }
        __syncthreads();
    }

    // Cross-thread reduction (red overlays A region — safe after final sync)
#pragma unroll
    for (int mt = 0; mt < 4; mt++)
#pragma unroll
        for (int h = 0; h < 2; h++) {
            int bi = mt * 2 + h;
            unsigned long long p =
                ((unsigned long long)f2ord(bestd[bi]) << 32) | (unsigned int)besti[bi];
            red[wm * 64 + mt * 16 + h * 8 + lr][wn * 4 + lk] = p;
        }
    __syncthreads();
    if (tid < BM) {
        unsigned long long b = red[tid][0];
#pragma unroll
        for (int q = 1; q < 16; q++) b = min(b, red[tid][q]);
        g_min_idx[m0 + tid] = (int)(b & 0xffffffffu);
    }
}

// ---------------------------------------------------------------------------
__global__ void epilogue_kernel(const float* __restrict__ X,
                                const float* __restrict__ R,
                                const float* __restrict__ C,
                                float* __restrict__ out) {
    int warp = (blockIdx.x * blockDim.x + threadIdx.x) >> 5;
    int lane = threadIdx.x & 31;
    if (warp >= NTOK) return;

    int idx = g_min_idx[warp];
    if (lane == 0) atomicAdd(&g_counts[idx], 1);

    const float4* xr = (const float4*)(X + (size_t)warp * DIM);
    const float4* rr = (const float4*)(R + (size_t)warp * DIM);
    const float4* cr = (const float4*)(C + (size_t)idx * DIM);

    float4 xs[2], rs[2];
    float r2 = 0.f, n2 = 0.f;
#pragma unroll
    for (int i = 0; i < 2; i++) {
        float4 x = xr[lane + 32 * i];
        float4 c = cr[lane + 32 * i];
        float4 r = rr[lane + 32 * i];
        xs[i] = x; rs[i] = r;
        float dx = x.x - c.x, dy = x.y - c.y, dz = x.z - c.z, dw = x.w - c.w;
        r2 += dx * dx + dy * dy + dz * dz + dw * dw;
        n2 += r.x * r.x + r.y * r.y + r.z * r.z + r.w * r.w;
    }
#pragma unroll
    for (int o = 16; o; o >>= 1) {
        r2 += __shfl_xor_sync(0xffffffffu, r2, o);
        n2 += __shfl_xor_sync(0xffffffffu, n2, o);
    }
    float scale = sqrtf(r2) / (sqrtf(n2) + EPSF);

    float4* orow = (float4*)(out + (size_t)warp * DIM);
#pragma unroll
    for (int i = 0; i < 2; i++) {
        float4 x = xs[i], r = rs[i], o4;
        o4.x = fmaf(scale, r.x, x.x);
        o4.y = fmaf(scale, r.y, x.y);
        o4.z = fmaf(scale, r.z, x.z);
        o4.w = fmaf(scale, r.w, x.w);
        orow[lane + 32 * i] = o4;
    }
}

// ---------------------------------------------------------------------------
__global__ void finalize_kernel(float* __restrict__ out, int out_size) {
    __shared__ float s_ent[32];
    __shared__ int   s_uni[32];
    int tid = threadIdx.x;

    float ent = 0.f;
    int   uni = 0;
    for (int i = tid; i < NCODE; i += blockDim.x) {
        int c = g_counts[i];
        if (c > 0) {
            uni++;
            float p = (float)c * (1.0f / (float)NTOK);
            ent += p * logf(p + EPSF);
        }
    }
#pragma unroll
    for (int o = 16; o; o >>= 1) {
        ent += __shfl_xor_sync(0xffffffffu, ent, o);
        uni += __shfl_xor_sync(0xffffffffu, uni, o);
    }
    int warp = tid >> 5, lane = tid & 31;
    if (lane == 0) { s_ent[warp] = ent; s_uni[warp] = uni; }
    __syncthreads();
    if (warp == 0) {
        int nw = (blockDim.x + 31) >> 5;
        ent = (lane < nw) ? s_ent[lane] : 0.f;
        uni = (lane < nw) ? s_uni[lane] : 0;
#pragma unroll
        for (int o = 16; o; o >>= 1) {
            ent += __shfl_xor_sync(0xffffffffu, ent, o);
            uni += __shfl_xor_sync(0xffffffffu, uni, o);
        }
        if (lane == 0) {
            long long base = (long long)NTOK * DIM;
            if (out_size > base)     out[base]     = expf(-ent);
            if (out_size > base + 1) out[base + 1] = (float)uni;
        }
    }
}

// ---------------------------------------------------------------------------
extern "C" void kernel_launch(void* const* d_in, const int* in_sizes, int n_in,
                              void* d_out, int out_size) {
    const float* X = (const float*)d_in[0];
    const float* R = (const float*)d_in[1];
    const float* C = (const float*)d_in[2];
    float* out = (float*)d_out;

    cudaFuncSetAttribute(argmin_mma_kernel,
                         cudaFuncAttributeMaxDynamicSharedMemorySize, SM_TOTAL);

    zero_counts_kernel<<<(NCODE + 255) / 256, 256>>>();
    convert_kernel<<<((NTOK + NCODE) * DIM / 4 + 255) / 256, 256>>>(X, C);
    cnorm_kernel<<<(NCODE * 32) / 256, 256>>>(C);
    argmin_mma_kernel<<<NTOK / BM, THREADS, SM_TOTAL>>>();
    epilogue_kernel<<<(NTOK * 32) / 256, 256>>>(X, R, C, out);
    finalize_kernel<<<1, 1024>>>(out, out_size);
}

// round 6
// speedup vs baseline: 8.6233x; 1.0066x over previous
#include <cuda_runtime.h>
#include <cuda_fp16.h>
#include <math.h>
#include <stdint.h>

#define NTOK  32768
#define NCODE 8192
#define DIM   256
#define EPSF  1e-8f

#define BM 128
#define BN 128
#define BK 64                    // K halfs per stage
#define NTILE (NCODE / BN)       // 64
#define NSTG  (NTILE * 4)        // 256 stages
#define THREADS 256

// smem geometry (bytes)
#define A_STRIDE 528
#define B_STRIDE 144
#define SM_B     (BM * A_STRIDE)             // 67584
#define B_BUF    (BM * B_STRIDE)             // 18432
#define SM_TOTAL (SM_B + 2 * B_BUF)          // 104448

// ---- scratch (no allocations allowed) ----
__device__ __half g_xh[NTOK * DIM];
__device__ __half g_ch[NCODE * DIM];
__device__ float  g_cnorm[NCODE];
__device__ int    g_min_idx[NTOK];
__device__ int    g_counts[NCODE];

__device__ __forceinline__ uint32_t smem_u32(const void* p) {
    uint32_t a;
    asm("{ .reg .u64 t; cvta.to.shared.u64 t, %1; cvt.u32.u64 %0, t; }"
        : "=r"(a) : "l"(p));
    return a;
}
__device__ __forceinline__ unsigned int f2ord(float f) {
    unsigned int u = __float_as_uint(f);
    return (u & 0x80000000u) ? ~u : (u | 0x80000000u);
}
#define CP_ASYNC16(dst, src) \
    asm volatile("cp.async.cg.shared.global [%0], [%1], 16;" :: "r"(dst), "l"(src))
#define CP_COMMIT() asm volatile("cp.async.commit_group;" ::: "memory")
#define CP_WAIT(n)  asm volatile("cp.async.wait_group %0;" :: "n"(n) : "memory")

#define LDSM_X4(r0, r1, r2, r3, addr) \
    asm volatile("ldmatrix.sync.aligned.m8n8.x4.shared.b16 {%0,%1,%2,%3}, [%4];" \
        : "=r"(r0), "=r"(r1), "=r"(r2), "=r"(r3) : "r"(addr))

// fp16-accumulator HMMA: D(half2 x2) = A*B + D
__device__ __forceinline__ void mma_f16acc(uint32_t& c0, uint32_t& c1,
                                           uint32_t a0, uint32_t a1, uint32_t a2, uint32_t a3,
                                           uint32_t b0, uint32_t b1) {
    asm volatile(
        "mma.sync.aligned.m16n8k16.row.col.f16.f16.f16.f16 "
        "{%0,%1}, {%2,%3,%4,%5}, {%6,%7}, {%0,%1};"
        : "+r"(c0), "+r"(c1)
        : "r"(a0), "r"(a1), "r"(a2), "r"(a3), "r"(b0), "r"(b1));
}

// ---------------------------------------------------------------------------
__global__ void zero_counts_kernel() {
    int i = blockIdx.x * blockDim.x + threadIdx.x;
    if (i < NCODE) g_counts[i] = 0;
}

__global__ void convert_kernel(const float* __restrict__ X,
                               const float* __restrict__ C) {
    const int nx = NTOK * DIM / 4;
    const int nc = NCODE * DIM / 4;
    int i = blockIdx.x * blockDim.x + threadIdx.x;
    if (i < nx) {
        float4 v = ((const float4*)X)[i];
        __half2* o = (__half2*)(g_xh + (size_t)i * 4);
        o[0] = __floats2half2_rn(v.x, v.y);
        o[1] = __floats2half2_rn(v.z, v.w);
    } else if (i < nx + nc) {
        int j = i - nx;
        float4 v = ((const float4*)C)[j];
        __half2* o = (__half2*)(g_ch + (size_t)j * 4);
        o[0] = __floats2half2_rn(v.x, v.y);
        o[1] = __floats2half2_rn(v.z, v.w);
    }
}

__global__ void cnorm_kernel(const float* __restrict__ cb) {
    int warp = (blockIdx.x * blockDim.x + threadIdx.x) >> 5;
    int lane = threadIdx.x & 31;
    if (warp >= NCODE) return;
    const float4* row = (const float4*)(cb + (size_t)warp * DIM);
    float s = 0.f;
#pragma unroll
    for (int i = 0; i < 2; i++) {
        float4 v = row[lane + 32 * i];
        s += v.x * v.x + v.y * v.y + v.z * v.z + v.w * v.w;
    }
#pragma unroll
    for (int o = 16; o; o >>= 1) s += __shfl_xor_sync(0xffffffffu, s, o);
    if (lane == 0) g_cnorm[warp] = s;
}

// ---------------------------------------------------------------------------
// fp16 mma.sync argmin GEMM: fp16 accumulators, double-buffered fragments,
// single __syncthreads per stage. A resident; B cp.async double-buffered.
// ---------------------------------------------------------------------------
__global__ __launch_bounds__(THREADS, 2)
void argmin_mma_kernel(void) {
    extern __shared__ __align__(16) char smem[];
    unsigned long long (*red)[17] = (unsigned long long (*)[17])smem;

    const int tid  = threadIdx.x;
    const int lane = tid & 31;
    const int wid  = tid >> 5;
    const int wm   = wid >> 2;
    const int wn   = wid & 3;
    const int lr   = lane >> 2;
    const int lk   = lane & 3;
    const int m0   = blockIdx.x * BM;

    const uint32_t sA = smem_u32(smem);
    const uint32_t sB = sA + SM_B;

    const uint32_t aBase = sA + (uint32_t)(wm * 64 + (lane & 15)) * A_STRIDE
                              + ((lane >> 4) & 1) * 16;
    const uint32_t bBase = (uint32_t)(wn * 32 + ((lane >> 4) & 1) * 8 + (lane & 7)) * B_STRIDE
                              + ((lane >> 3) & 1) * 16;

    // Prefetch resident A + B(0) as one group
    {
        const __half* xa = g_xh + (size_t)m0 * DIM;
#pragma unroll
        for (int r = 0; r < 16; r++) {
            int c   = tid + r * THREADS;
            int row = c >> 5, q = c & 31;
            CP_ASYNC16(sA + row * A_STRIDE + q * 16, xa + (size_t)row * DIM + q * 8);
        }
#pragma unroll
        for (int r = 0; r < 4; r++) {
            int c   = tid + r * THREADS;
            int row = c >> 3, q = c & 7;
            CP_ASYNC16(sB + row * B_STRIDE + q * 16, g_ch + (size_t)row * DIM + q * 8);
        }
        CP_COMMIT();
    }

    float bestd[8];
    int   besti[8];
#pragma unroll
    for (int i = 0; i < 8; i++) { bestd[i] = __int_as_float(0x7f800000); besti[i] = 0; }

    uint32_t acc[4][4][2];       // packed half2 accumulators
    uint32_t af[2][4][4];        // double-buffered A fragments
    uint32_t bf[2][4][2];        // double-buffered B fragments

    for (int s = 0; s < NSTG; s++) {
        CP_WAIT(0);
        __syncthreads();          // single barrier: publishes buf s, frees buf s+1

        // issue prefetch of stage s+1 (overlaps compute of s)
        if (s + 1 < NSTG) {
            const int t1 = (s + 1) >> 2, k1 = (s + 1) & 3;
            const uint32_t d = sB + ((s + 1) & 1) * B_BUF;
            const __half* src = g_ch + (size_t)t1 * BN * DIM + k1 * BK;
#pragma unroll
            for (int r = 0; r < 4; r++) {
                int c   = tid + r * THREADS;
                int row = c >> 3, q = c & 7;
                CP_ASYNC16(d + row * B_STRIDE + q * 16, src + (size_t)row * DIM + q * 8);
            }
            CP_COMMIT();
        }

        const int ks = s & 3;
        const uint32_t aK = aBase + ks * 128;
        const uint32_t bK = sB + (s & 1) * B_BUF + bBase;

        if (ks == 0) {
#pragma unroll
            for (int mt = 0; mt < 4; mt++)
#pragma unroll
                for (int nt = 0; nt < 4; nt++) {
                    acc[mt][nt][0] = 0u; acc[mt][nt][1] = 0u;
                }
        }

        // preload fragments for kk=0
#pragma unroll
        for (int mt = 0; mt < 4; mt++)
            LDSM_X4(af[0][mt][0], af[0][mt][1], af[0][mt][2], af[0][mt][3],
                    aK + mt * (16 * A_STRIDE));
#pragma unroll
        for (int p = 0; p < 2; p++)
            LDSM_X4(bf[0][2 * p][0], bf[0][2 * p][1], bf[0][2 * p + 1][0], bf[0][2 * p + 1][1],
                    bK + p * (16 * B_STRIDE));

#pragma unroll
        for (int kk = 0; kk < 4; kk++) {
            const int cur = kk & 1, nxt = cur ^ 1;
            if (kk < 3) {   // prefetch next kk's fragments before this kk's MMAs
#pragma unroll
                for (int mt = 0; mt < 4; mt++)
                    LDSM_X4(af[nxt][mt][0], af[nxt][mt][1], af[nxt][mt][2], af[nxt][mt][3],
                            aK + (kk + 1) * 32 + mt * (16 * A_STRIDE));
#pragma unroll
                for (int p = 0; p < 2; p++)
                    LDSM_X4(bf[nxt][2 * p][0], bf[nxt][2 * p][1],
                            bf[nxt][2 * p + 1][0], bf[nxt][2 * p + 1][1],
                            bK + (kk + 1) * 32 + p * (16 * B_STRIDE));
            }
#pragma unroll
            for (int mt = 0; mt < 4; mt++)
#pragma unroll
                for (int nt = 0; nt < 4; nt++)
                    mma_f16acc(acc[mt][nt][0], acc[mt][nt][1],
                               af[cur][mt][0], af[cur][mt][1], af[cur][mt][2], af[cur][mt][3],
                               bf[cur][nt][0], bf[cur][nt][1]);
        }

        if (ks == 3) {
            const int n0 = (s >> 2) * BN;
#pragma unroll
            for (int nt = 0; nt < 4; nt++) {
                int col = n0 + wn * 32 + nt * 8 + 2 * lk;
                float cn0 = __ldg(&g_cnorm[col]);
                float cn1 = __ldg(&g_cnorm[col + 1]);
#pragma unroll
                for (int mt = 0; mt < 4; mt++) {
#pragma unroll
                    for (int h = 0; h < 2; h++) {
                        int bi = mt * 2 + h;
                        float2 dv = __half22float2(*(__half2*)&acc[mt][nt][h]);
                        float d0 = fmaf(-2.f, dv.x, cn0);
                        float d1 = fmaf(-2.f, dv.y, cn1);
                        if (d0 < bestd[bi]) { bestd[bi] = d0; besti[bi] = col; }
                        if (d1 < bestd[bi]) { bestd[bi] = d1; besti[bi] = col + 1; }
                    }
                }
            }
        }
    }

    // Cross-thread reduction (red overlays A region — safe after final sync)
    __syncthreads();
#pragma unroll
    for (int mt = 0; mt < 4; mt++)
#pragma unroll
        for (int h = 0; h < 2; h++) {
            int bi = mt * 2 + h;
            unsigned long long p =
                ((unsigned long long)f2ord(bestd[bi]) << 32) | (unsigned int)besti[bi];
            red[wm * 64 + mt * 16 + h * 8 + lr][wn * 4 + lk] = p;
        }
    __syncthreads();
    if (tid < BM) {
        unsigned long long b = red[tid][0];
#pragma unroll
        for (int q = 1; q < 16; q++) b = min(b, red[tid][q]);
        g_min_idx[m0 + tid] = (int)(b & 0xffffffffu);
    }
}

// ---------------------------------------------------------------------------
__global__ void epilogue_kernel(const float* __restrict__ X,
                                const float* __restrict__ R,
                                const float* __restrict__ C,
                                float* __restrict__ out) {
    int warp = (blockIdx.x * blockDim.x + threadIdx.x) >> 5;
    int lane = threadIdx.x & 31;
    if (warp >= NTOK) return;

    int idx = g_min_idx[warp];
    if (lane == 0) atomicAdd(&g_counts[idx], 1);

    const float4* xr = (const float4*)(X + (size_t)warp * DIM);
    const float4* rr = (const float4*)(R + (size_t)warp * DIM);
    const float4* cr = (const float4*)(C + (size_t)idx * DIM);

    float4 xs[2], rs[2];
    float r2 = 0.f, n2 = 0.f;
#pragma unroll
    for (int i = 0; i < 2; i++) {
        float4 x = xr[lane + 32 * i];
        float4 c = cr[lane + 32 * i];
        float4 r = rr[lane + 32 * i];
        xs[i] = x; rs[i] = r;
        float dx = x.x - c.x, dy = x.y - c.y, dz = x.z - c.z, dw = x.w - c.w;
        r2 += dx * dx + dy * dy + dz * dz + dw * dw;
        n2 += r.x * r.x + r.y * r.y + r.z * r.z + r.w * r.w;
    }
#pragma unroll
    for (int o = 16; o; o >>= 1) {
        r2 += __shfl_xor_sync(0xffffffffu, r2, o);
        n2 += __shfl_xor_sync(0xffffffffu, n2, o);
    }
    float scale = sqrtf(r2) / (sqrtf(n2) + EPSF);

    float4* orow = (float4*)(out + (size_t)warp * DIM);
#pragma unroll
    for (int i = 0; i < 2; i++) {
        float4 x = xs[i], r = rs[i], o4;
        o4.x = fmaf(scale, r.x, x.x);
        o4.y = fmaf(scale, r.y, x.y);
        o4.z = fmaf(scale, r.z, x.z);
        o4.w = fmaf(scale, r.w, x.w);
        orow[lane + 32 * i] = o4;
    }
}

// ---------------------------------------------------------------------------
__global__ void finalize_kernel(float* __restrict__ out, int out_size) {
    __shared__ float s_ent[32];
    __shared__ int   s_uni[32];
    int tid = threadIdx.x;

    float ent = 0.f;
    int   uni = 0;
    for (int i = tid; i < NCODE; i += blockDim.x) {
        int c = g_counts[i];
        if (c > 0) {
            uni++;
            float p = (float)c * (1.0f / (float)NTOK);
            ent += p * logf(p + EPSF);
        }
    }
#pragma unroll
    for (int o = 16; o; o >>= 1) {
        ent += __shfl_xor_sync(0xffffffffu, ent, o);
        uni += __shfl_xor_sync(0xffffffffu, uni, o);
    }
    int warp = tid >> 5, lane = tid & 31;
    if (lane == 0) { s_ent[warp] = ent; s_uni[warp] = uni; }
    __syncthreads();
    if (warp == 0) {
        int nw = (blockDim.x + 31) >> 5;
        ent = (lane < nw) ? s_ent[lane] : 0.f;
        uni = (lane < nw) ? s_uni[lane] : 0;
#pragma unroll
        for (int o = 16; o; o >>= 1) {
            ent += __shfl_xor_sync(0xffffffffu, ent, o);
            uni += __shfl_xor_sync(0xffffffffu, uni, o);
        }
        if (lane == 0) {
            long long base = (long long)NTOK * DIM;
            if (out_size > base)     out[base]     = expf(-ent);
            if (out_size > base + 1) out[base + 1] = (float)uni;
        }
    }
}

// ---------------------------------------------------------------------------
extern "C" void kernel_launch(void* const* d_in, const int* in_sizes, int n_in,
                              void* d_out, int out_size) {
    const float* X = (const float*)d_in[0];
    const float* R = (const float*)d_in[1];
    const float* C = (const float*)d_in[2];
    float* out = (float*)d_out;

    cudaFuncSetAttribute(argmin_mma_kernel,
                         cudaFuncAttributeMaxDynamicSharedMemorySize, SM_TOTAL);

    zero_counts_kernel<<<(NCODE + 255) / 256, 256>>>();
    convert_kernel<<<((NTOK + NCODE) * DIM / 4 + 255) / 256, 256>>>(X, C);
    cnorm_kernel<<<(NCODE * 32) / 256, 256>>>(C);
    argmin_mma_kernel<<<NTOK / BM, THREADS, SM_TOTAL>>>();
    epilogue_kernel<<<(NTOK * 32) / 256, 256>>>(X, R, C, out);
    finalize_kernel<<<1, 1024>>>(out, out_size);
}

// round 7
// speedup vs baseline: 9.5051x; 1.1022x over previous
#include <cuda_runtime.h>
#include <cuda_fp16.h>
#include <math.h>
#include <stdint.h>

#define NTOK  32768
#define NCODE 8192
#define DIM   256
#define EPSF  1e-8f

#define BM 128
#define BN 128
#define BK 32                    // K halfs per stage (per-warp private B chunk)
#define NTILE (NCODE / BN)       // 64
#define KSTG  (DIM / BK)         // 8 stages per tile
#define NSTG  (NTILE * KSTG)     // 512 stages
#define THREADS 256

// smem geometry (bytes)
#define A_STRIDE 528             // 132 words (== 4 mod 32): conflict-free ldmatrix
#define B_STRIDE 80              // 20 words: 20r mod 32 distinct over r=0..7
#define SM_B     (BM * A_STRIDE)             // 67584
#define BW_BUF   (32 * B_STRIDE)             // 2560 per warp-buffer
#define SM_TOTAL (SM_B + 8 * 2 * BW_BUF)     // 108544

// ---- scratch (no allocations allowed) ----
__device__ __half g_xh[NTOK * DIM];
__device__ __half g_ch[NCODE * DIM];
__device__ float  g_cnorm[NCODE];
__device__ int    g_min_idx[NTOK];
__device__ int    g_counts[NCODE];

__device__ __forceinline__ uint32_t smem_u32(const void* p) {
    uint32_t a;
    asm("{ .reg .u64 t; cvta.to.shared.u64 t, %1; cvt.u32.u64 %0, t; }"
        : "=r"(a) : "l"(p));
    return a;
}
__device__ __forceinline__ unsigned int f2ord(float f) {
    unsigned int u = __float_as_uint(f);
    return (u & 0x80000000u) ? ~u : (u | 0x80000000u);
}
#define CP_ASYNC16(dst, src) \
    asm volatile("cp.async.cg.shared.global [%0], [%1], 16;" :: "r"(dst), "l"(src))
#define CP_COMMIT() asm volatile("cp.async.commit_group;" ::: "memory")
#define CP_WAIT(n)  asm volatile("cp.async.wait_group %0;" :: "n"(n) : "memory")

#define LDSM_X4(r0, r1, r2, r3, addr) \
    asm volatile("ldmatrix.sync.aligned.m8n8.x4.shared.b16 {%0,%1,%2,%3}, [%4];" \
        : "=r"(r0), "=r"(r1), "=r"(r2), "=r"(r3) : "r"(addr))

__device__ __forceinline__ void mma_f16(float& c0, float& c1, float& c2, float& c3,
                                        uint32_t a0, uint32_t a1, uint32_t a2, uint32_t a3,
                                        uint32_t b0, uint32_t b1) {
    asm volatile(
        "mma.sync.aligned.m16n8k16.row.col.f32.f16.f16.f32 "
        "{%0,%1,%2,%3}, {%4,%5,%6,%7}, {%8,%9}, {%0,%1,%2,%3};"
        : "+f"(c0), "+f"(c1), "+f"(c2), "+f"(c3)
        : "r"(a0), "r"(a1), "r"(a2), "r"(a3), "r"(b0), "r"(b1));
}

// ---------------------------------------------------------------------------
__global__ void zero_counts_kernel() {
    int i = blockIdx.x * blockDim.x + threadIdx.x;
    if (i < NCODE) g_counts[i] = 0;
}

__global__ void convert_kernel(const float* __restrict__ X,
                               const float* __restrict__ C) {
    const int nx = NTOK * DIM / 4;
    const int nc = NCODE * DIM / 4;
    int i = blockIdx.x * blockDim.x + threadIdx.x;
    if (i < nx) {
        float4 v = ((const float4*)X)[i];
        __half2* o = (__half2*)(g_xh + (size_t)i * 4);
        o[0] = __floats2half2_rn(v.x, v.y);
        o[1] = __floats2half2_rn(v.z, v.w);
    } else if (i < nx + nc) {
        int j = i - nx;
        float4 v = ((const float4*)C)[j];
        __half2* o = (__half2*)(g_ch + (size_t)j * 4);
        o[0] = __floats2half2_rn(v.x, v.y);
        o[1] = __floats2half2_rn(v.z, v.w);
    }
}

__global__ void cnorm_kernel(const float* __restrict__ cb) {
    int warp = (blockIdx.x * blockDim.x + threadIdx.x) >> 5;
    int lane = threadIdx.x & 31;
    if (warp >= NCODE) return;
    const float4* row = (const float4*)(cb + (size_t)warp * DIM);
    float s = 0.f;
#pragma unroll
    for (int i = 0; i < 2; i++) {
        float4 v = row[lane + 32 * i];
        s += v.x * v.x + v.y * v.y + v.z * v.z + v.w * v.w;
    }
#pragma unroll
    for (int o = 16; o; o >>= 1) s += __shfl_xor_sync(0xffffffffu, s, o);
    if (lane == 0) g_cnorm[warp] = s;
}

// ---------------------------------------------------------------------------
// Barrier-free fp16 mma.sync argmin GEMM.
// A resident (read-only). Each warp owns a private double-buffered B slice
// (its 32 n-columns x 32 k), fed by its own cp.async groups. No __syncthreads
// in the main loop -> no barrier convoy; warps free-run.
// ---------------------------------------------------------------------------
__global__ __launch_bounds__(THREADS, 2)
void argmin_mma_kernel(void) {
    extern __shared__ __align__(16) char smem[];
    unsigned long long (*red)[17] = (unsigned long long (*)[17])smem;

    const int tid  = threadIdx.x;
    const int lane = tid & 31;
    const int wid  = tid >> 5;
    const int wm   = wid >> 2;          // 0..1
    const int wn   = wid & 3;           // 0..3
    const int lr   = lane >> 2;
    const int lk   = lane & 3;
    const int m0   = blockIdx.x * BM;

    const uint32_t sA = smem_u32(smem);
    const uint32_t sBW = sA + SM_B + wid * (2 * BW_BUF);   // this warp's B slices

    // ldmatrix lane bases
    const uint32_t aBase = sA + (uint32_t)(wm * 64 + (lane & 15)) * A_STRIDE
                              + ((lane >> 4) & 1) * 16;
    const uint32_t bFragOff = (uint32_t)(((lane >> 4) & 1) * 8 + (lane & 7)) * B_STRIDE
                              + ((lane >> 3) & 1) * 16;

    // per-lane cp.async geometry for the warp's B slice (32 rows x 64B)
    const int bRow0 = lane >> 2;        // with i-step 8: rows lane/4 + 8i
    const int bQ    = lane & 3;
    const __half* bSrcBase = g_ch + (size_t)(wn * 32) * DIM;   // + n0*DIM + ks*BK

    // --- init: cooperative A load + this warp's B(0); one barrier total ---
    {
        const __half* xa = g_xh + (size_t)m0 * DIM;
#pragma unroll
        for (int r = 0; r < 16; r++) {
            int c   = tid + r * THREADS;
            int row = c >> 5, q = c & 31;
            CP_ASYNC16(sA + row * A_STRIDE + q * 16, xa + (size_t)row * DIM + q * 8);
        }
#pragma unroll
        for (int i = 0; i < 4; i++) {
            int row = bRow0 + 8 * i;
            CP_ASYNC16(sBW + row * B_STRIDE + bQ * 16,
                       bSrcBase + (size_t)row * DIM + bQ * 8);
        }
        CP_COMMIT();
        CP_WAIT(0);
        __syncthreads();   // publish A to all warps (only barrier before the end)
    }

    float bestd[8];
    int   besti[8];
#pragma unroll
    for (int i = 0; i < 8; i++) { bestd[i] = __int_as_float(0x7f800000); besti[i] = 0; }

    float acc[4][4][4];

    for (int s = 0; s < NSTG; s++) {
        // prefetch this warp's B slice for stage s+1 (private buffer, no hazard:
        // its previous reader was compute(s-1), already issued in program order)
        if (s + 1 < NSTG) {
            const int t1 = (s + 1) >> 3, k1 = (s + 1) & 7;
            const uint32_t d = sBW + ((s + 1) & 1) * BW_BUF;
            const __half* src = bSrcBase + (size_t)t1 * BN * DIM + k1 * BK;
#pragma unroll
            for (int i = 0; i < 4; i++) {
                int row = bRow0 + 8 * i;
                CP_ASYNC16(d + row * B_STRIDE + bQ * 16, src + (size_t)row * DIM + bQ * 8);
            }
            CP_COMMIT();
            CP_WAIT(1);    // group s done; s+1 in flight
        } else {
            CP_WAIT(0);
        }

        const int ks = s & 7;
        const uint32_t aK = aBase + ks * 64;                   // + kk*32 + mt*16*A_STRIDE
        const uint32_t bK = sBW + (s & 1) * BW_BUF + bFragOff; // + kk*32 + p*16*B_STRIDE

        if (ks == 0) {
#pragma unroll
            for (int mt = 0; mt < 4; mt++)
#pragma unroll
                for (int nt = 0; nt < 4; nt++)
#pragma unroll
                    for (int e = 0; e < 4; e++) acc[mt][nt][e] = 0.f;
        }

#pragma unroll
        for (int kk = 0; kk < 2; kk++) {
            uint32_t af[4][4];
#pragma unroll
            for (int mt = 0; mt < 4; mt++)
                LDSM_X4(af[mt][0], af[mt][1], af[mt][2], af[mt][3],
                        aK + kk * 32 + mt * (16 * A_STRIDE));
            uint32_t bf[4][2];
#pragma unroll
            for (int p = 0; p < 2; p++)
                LDSM_X4(bf[2 * p][0], bf[2 * p][1], bf[2 * p + 1][0], bf[2 * p + 1][1],
                        bK + kk * 32 + p * (16 * B_STRIDE));
#pragma unroll
            for (int mt = 0; mt < 4; mt++)
#pragma unroll
                for (int nt = 0; nt < 4; nt++)
                    mma_f16(acc[mt][nt][0], acc[mt][nt][1],
                            acc[mt][nt][2], acc[mt][nt][3],
                            af[mt][0], af[mt][1], af[mt][2], af[mt][3],
                            bf[nt][0], bf[nt][1]);
        }

        if (ks == 7) {
            const int n0 = (s >> 3) * BN;
#pragma unroll
            for (int nt = 0; nt < 4; nt++) {
                int col = n0 + wn * 32 + nt * 8 + 2 * lk;
                float cn0 = __ldg(&g_cnorm[col]);
                float cn1 = __ldg(&g_cnorm[col + 1]);
#pragma unroll
                for (int mt = 0; mt < 4; mt++) {
#pragma unroll
                    for (int h = 0; h < 2; h++) {
                        int bi = mt * 2 + h;
                        float d0 = fmaf(-2.f, acc[mt][nt][2 * h], cn0);
                        float d1 = fmaf(-2.f, acc[mt][nt][2 * h + 1], cn1);
                        if (d0 < bestd[bi]) { bestd[bi] = d0; besti[bi] = col; }
                        if (d1 < bestd[bi]) { bestd[bi] = d1; besti[bi] = col + 1; }
                    }
                }
            }
        }
    }

    // Cross-thread reduction (red overlays A region — safe after this sync)
    __syncthreads();
#pragma unroll
    for (int mt = 0; mt < 4; mt++)
#pragma unroll
        for (int h = 0; h < 2; h++) {
            int bi = mt * 2 + h;
            unsigned long long p =
                ((unsigned long long)f2ord(bestd[bi]) << 32) | (unsigned int)besti[bi];
            red[wm * 64 + mt * 16 + h * 8 + lr][wn * 4 + lk] = p;
        }
    __syncthreads();
    if (tid < BM) {
        unsigned long long b = red[tid][0];
#pragma unroll
        for (int q = 1; q < 16; q++) b = min(b, red[tid][q]);
        g_min_idx[m0 + tid] = (int)(b & 0xffffffffu);
    }
}

// ---------------------------------------------------------------------------
__global__ void epilogue_kernel(const float* __restrict__ X,
                                const float* __restrict__ R,
                                const float* __restrict__ C,
                                float* __restrict__ out) {
    int warp = (blockIdx.x * blockDim.x + threadIdx.x) >> 5;
    int lane = threadIdx.x & 31;
    if (warp >= NTOK) return;

    int idx = g_min_idx[warp];
    if (lane == 0) atomicAdd(&g_counts[idx], 1);

    const float4* xr = (const float4*)(X + (size_t)warp * DIM);
    const float4* rr = (const float4*)(R + (size_t)warp * DIM);
    const float4* cr = (const float4*)(C + (size_t)idx * DIM);

    float4 xs[2], rs[2];
    float r2 = 0.f, n2 = 0.f;
#pragma unroll
    for (int i = 0; i < 2; i++) {
        float4 x = xr[lane + 32 * i];
        float4 c = cr[lane + 32 * i];
        float4 r = rr[lane + 32 * i];
        xs[i] = x; rs[i] = r;
        float dx = x.x - c.x, dy = x.y - c.y, dz = x.z - c.z, dw = x.w - c.w;
        r2 += dx * dx + dy * dy + dz * dz + dw * dw;
        n2 += r.x * r.x + r.y * r.y + r.z * r.z + r.w * r.w;
    }
#pragma unroll
    for (int o = 16; o; o >>= 1) {
        r2 += __shfl_xor_sync(0xffffffffu, r2, o);
        n2 += __shfl_xor_sync(0xffffffffu, n2, o);
    }
    float scale = sqrtf(r2) / (sqrtf(n2) + EPSF);

    float4* orow = (float4*)(out + (size_t)warp * DIM);
#pragma unroll
    for (int i = 0; i < 2; i++) {
        float4 x = xs[i], r = rs[i], o4;
        o4.x = fmaf(scale, r.x, x.x);
        o4.y = fmaf(scale, r.y, x.y);
        o4.z = fmaf(scale, r.z, x.z);
        o4.w = fmaf(scale, r.w, x.w);
        orow[lane + 32 * i] = o4;
    }
}

// ---------------------------------------------------------------------------
__global__ void finalize_kernel(float* __restrict__ out, int out_size) {
    __shared__ float s_ent[32];
    __shared__ int   s_uni[32];
    int tid = threadIdx.x;

    float ent = 0.f;
    int   uni = 0;
    for (int i = tid; i < NCODE; i += blockDim.x) {
        int c = g_counts[i];
        if (c > 0) {
            uni++;
            float p = (float)c * (1.0f / (float)NTOK);
            ent += p * logf(p + EPSF);
        }
    }
#pragma unroll
    for (int o = 16; o; o >>= 1) {
        ent += __shfl_xor_sync(0xffffffffu, ent, o);
        uni += __shfl_xor_sync(0xffffffffu, uni, o);
    }
    int warp = tid >> 5, lane = tid & 31;
    if (lane == 0) { s_ent[warp] = ent; s_uni[warp] = uni; }
    __syncthreads();
    if (warp == 0) {
        int nw = (blockDim.x + 31) >> 5;
        ent = (lane < nw) ? s_ent[lane] : 0.f;
        uni = (lane < nw) ? s_uni[lane] : 0;
#pragma unroll
        for (int o = 16; o; o >>= 1) {
            ent += __shfl_xor_sync(0xffffffffu, ent, o);
            uni += __shfl_xor_sync(0xffffffffu, uni, o);
        }
        if (lane == 0) {
            long long base = (long long)NTOK * DIM;
            if (out_size > base)     out[base]     = expf(-ent);
            if (out_size > base + 1) out[base + 1] = (float)uni;
        }
    }
}

// ---------------------------------------------------------------------------
extern "C" void kernel_launch(void* const* d_in, const int* in_sizes, int n_in,
                              void* d_out, int out_size) {
    const float* X = (const float*)d_in[0];
    const float* R = (const float*)d_in[1];
    const float* C = (const float*)d_in[2];
    float* out = (float*)d_out;

    cudaFuncSetAttribute(argmin_mma_kernel,
                         cudaFuncAttributeMaxDynamicSharedMemorySize, SM_TOTAL);

    zero_counts_kernel<<<(NCODE + 255) / 256, 256>>>();
    convert_kernel<<<((NTOK + NCODE) * DIM / 4 + 255) / 256, 256>>>(X, C);
    cnorm_kernel<<<(NCODE * 32) / 256, 256>>>(C);
    argmin_mma_kernel<<<NTOK / BM, THREADS, SM_TOTAL>>>();
    epilogue_kernel<<<(NTOK * 32) / 256, 256>>>(X, R, C, out);
    finalize_kernel<<<1, 1024>>>(out, out_size);
}